// round 8
// baseline (speedup 1.0000x reference)
#include <cuda_runtime.h>

#define H       20
#define SEQ     512
#define NB      4096
#define BPB     6                 // batches per block (120 compute + 8 head lanes)
#define THREADS 128
#define GRID    ((NB + BPB - 1) / BPB)   // 683

typedef unsigned long long u64;

__device__ __forceinline__ u64 pack2(float a, float b) {
    u64 r; asm("mov.b64 %0, {%1,%2};" : "=l"(r) : "f"(a), "f"(b)); return r;
}
__device__ __forceinline__ void unpack2(u64 v, float& a, float& b) {
    asm("mov.b64 {%0,%1}, %2;" : "=f"(a), "=f"(b) : "l"(v));
}
// Blackwell packed fp32 math (f32x2, PTX-only)
__device__ __forceinline__ u64 fma2(u64 a, u64 b, u64 c) {
    u64 d; asm("fma.rn.f32x2 %0, %1, %2, %3;" : "=l"(d) : "l"(a), "l"(b), "l"(c)); return d;
}
__device__ __forceinline__ u64 add2(u64 a, u64 b) {
    u64 d; asm("add.rn.f32x2 %0, %1, %2;" : "=l"(d) : "l"(a), "l"(b)); return d;
}
__device__ __forceinline__ float ex2_(float v) {
    float r; asm("ex2.approx.f32 %0, %1;" : "=f"(r) : "f"(v)); return r;
}
__device__ __forceinline__ float rcp_(float v) {
    float r; asm("rcp.approx.f32 %0, %1;" : "=f"(r) : "f"(v)); return r;
}
#define L2E 1.4426950408889634f
__device__ __forceinline__ float sigmoidf_(float v) {
    return rcp_(1.0f + ex2_(v * -L2E));
}
__device__ __forceinline__ float tanhf_(float v) {
    return fmaf(2.0f, rcp_(1.0f + ex2_(v * -2.0f * L2E)), -1.0f);
}

__global__ __launch_bounds__(THREADS, 5) void lstm_fused(
    const float* __restrict__ x,     const float* __restrict__ W_ih,
    const float* __restrict__ W_hh,  const float* __restrict__ b_ih,
    const float* __restrict__ b_hh,  const float* __restrict__ W_lin,
    const float* __restrict__ b_lin, float* __restrict__ out)
{
    // double-buffered h, duplicated {h,h} so LDS.128 feeds fma2 directly
    __shared__ __align__(16) float2 hbuf[2][BPB][H];
    // double-buffered h*W_lin partials for head lanes (pad 24 -> 96B rows)
    __shared__ __align__(16) float  psum[2][BPB][24];
    __shared__ float xs[BPB * SEQ];   // staged x rows (12 KB)

    const int tid  = threadIdx.x;
    const int b    = tid / H;               // local batch  (compute lanes)
    const int j    = tid % H;               // hidden unit  (compute lanes)
    const bool comp = tid < BPB * H;        // 120 compute lanes
    const int  hs   = tid - BPB * H;        // head slot on spare lanes
    const bool hact = (hs >= 0) && (hs < BPB) && (blockIdx.x * BPB + hs < NB);

    // Stage x for all 6 batches (coalesced; clamp out-of-range batch).
    for (int i = tid; i < BPB * SEQ; i += THREADS) {
        int gbx = blockIdx.x * BPB + (i >> 9);
        if (gbx > NB - 1) gbx = NB - 1;
        xs[i] = x[(size_t)gbx * SEQ + (i & (SEQ - 1))];
    }

    // All recurrent weights in registers: lane j owns gate rows
    // j(i), H+j(f), 2H+j(g), 3H+j(o), packed (i,f) and (g,o) -> 80 regs.
    u64 wif[H], wgo[H];
    u64 bif = 0, bgo = 0, wxif = 0, wxgo = 0;
    float wl = 0.0f;
    if (comp) {
#pragma unroll
        for (int k = 0; k < H; ++k) {
            wif[k] = pack2(W_hh[j * H + k],           W_hh[(H + j) * H + k]);
            wgo[k] = pack2(W_hh[(2 * H + j) * H + k], W_hh[(3 * H + j) * H + k]);
        }
        bif  = pack2(b_ih[j] + b_hh[j],             b_ih[H + j] + b_hh[H + j]);
        bgo  = pack2(b_ih[2 * H + j] + b_hh[2 * H + j],
                     b_ih[3 * H + j] + b_hh[3 * H + j]);
        wxif = pack2(W_ih[j],         W_ih[H + j]);
        wxgo = pack2(W_ih[2 * H + j], W_ih[3 * H + j]);
        wl   = W_lin[j];
        hbuf[0][b][j] = make_float2(0.0f, 0.0f);
    }
    const float bl = b_lin[0];
    float* ohead = hact ? (out + (size_t)(blockIdx.x * BPB + hs) * SEQ) : out;
    const float* xrow = xs + ((comp ? b : 0) << 9);
    const int bloc = comp ? b : 0;
    const int hloc = hact ? hs : 0;

    __syncthreads();   // covers xs preload + h init

    float c = 0.0f;

#pragma unroll 2
    for (int t = 0; t < SEQ; ++t) {
        const int r = t & 1, w = r ^ 1;
        if (comp) {
            const longlong2* hp = (const longlong2*)&hbuf[r][bloc][0];
            float xt = xrow[t];
            u64 x2 = pack2(xt, xt);

            // single accumulator chain per gate pair (saves regs; 10 chains
            // per SMSP keep the fma pipe throughput-bound, not latency-bound)
            u64 aIF = bif, aGO = bgo;
#pragma unroll
            for (int q = 0; q < H / 2; ++q) {
                longlong2 hh = hp[q];     // {h2q,h2q},{h2q+1,h2q+1} broadcast
                aIF = fma2((u64)hh.x, wif[2 * q],     aIF);
                aIF = fma2((u64)hh.y, wif[2 * q + 1], aIF);
                aGO = fma2((u64)hh.x, wgo[2 * q],     aGO);
                aGO = fma2((u64)hh.y, wgo[2 * q + 1], aGO);
            }
            u64 gIF = fma2(x2, wxif, aIF);
            u64 gGO = fma2(x2, wxgo, aGO);

            float gi, gf, gg, go;
            unpack2(gIF, gi, gf);
            unpack2(gGO, gg, go);
            float iv = sigmoidf_(gi);
            float fv = sigmoidf_(gf);
            float gv = tanhf_(gg);
            float ov = sigmoidf_(go);
            c = fmaf(fv, c, iv * gv);
            float h = ov * tanhf_(c);

            hbuf[w][bloc][j] = make_float2(h, h);
            psum[w][bloc][j] = h * wl;
        }
        __syncthreads();
        if (hact) {
            // 20 partials -> packed add2 tree (5 LDS.128 + 9 add2)
            const ulonglong2* pq = (const ulonglong2*)&psum[w][hloc][0];
            ulonglong2 p0 = pq[0], p1 = pq[1], p2 = pq[2], p3 = pq[3], p4 = pq[4];
            u64 s0 = add2((u64)p0.x, (u64)p0.y);
            u64 s1 = add2((u64)p1.x, (u64)p1.y);
            u64 s2 = add2((u64)p2.x, (u64)p2.y);
            u64 s3 = add2((u64)p3.x, (u64)p3.y);
            u64 s4 = add2((u64)p4.x, (u64)p4.y);
            u64 s = add2(add2(add2(s0, s1), add2(s2, s3)), s4);
            float lo, hi;
            unpack2(s, lo, hi);
            ohead[t] = lo + hi + bl;
        }
    }
}

extern "C" void kernel_launch(void* const* d_in, const int* in_sizes, int n_in,
                              void* d_out, int out_size) {
    const float* x     = (const float*)d_in[0];
    const float* W_ih  = (const float*)d_in[1];
    const float* W_hh  = (const float*)d_in[2];
    const float* b_ih  = (const float*)d_in[3];
    const float* b_hh  = (const float*)d_in[4];
    const float* W_lin = (const float*)d_in[5];
    const float* b_lin = (const float*)d_in[6];
    float* out = (float*)d_out;

    lstm_fused<<<GRID, THREADS>>>(x, W_ih, W_hh, b_ih, b_hh, W_lin, b_lin, out);
}

// round 9
// speedup vs baseline: 1.0916x; 1.0916x over previous
#include <cuda_runtime.h>
#include <cstdint>

#define H       20
#define SEQ     512
#define NB      4096
#define BPB     16                  // batches per block (mma M=16)
#define THREADS 128
#define GRID    (NB / BPB)          // 256
#define XP      516                 // xs row stride (floats): 16B-aligned, bank-spread

typedef unsigned int u32;

__device__ __forceinline__ u32 cvt_tf32(float f) {
    u32 r; asm("cvt.rna.tf32.f32 %0, %1;" : "=r"(r) : "f"(f)); return r;
}
__device__ __forceinline__ float ex2_(float v) {
    float r; asm("ex2.approx.f32 %0, %1;" : "=f"(r) : "f"(v)); return r;
}
__device__ __forceinline__ float rcp_(float v) {
    float r; asm("rcp.approx.f32 %0, %1;" : "=f"(r) : "f"(v)); return r;
}
#define L2E 1.4426950408889634f
__device__ __forceinline__ float sigmoidf_(float v) {
    return rcp_(1.0f + ex2_(v * -L2E));
}
__device__ __forceinline__ float tanhf_(float v) {
    return fmaf(2.0f, rcp_(1.0f + ex2_(v * -2.0f * L2E)), -1.0f);
}

// D = A*B + C   (m16n8k8 tf32), C given explicitly (bias init)
__device__ __forceinline__ void mma_init(float* d, const u32* a, const u32* b,
                                         float c0, float c1, float c2, float c3) {
    asm("mma.sync.aligned.m16n8k8.row.col.f32.tf32.tf32.f32 "
        "{%0,%1,%2,%3}, {%4,%5,%6,%7}, {%8,%9}, {%10,%11,%12,%13};"
        : "=f"(d[0]), "=f"(d[1]), "=f"(d[2]), "=f"(d[3])
        : "r"(a[0]), "r"(a[1]), "r"(a[2]), "r"(a[3]), "r"(b[0]), "r"(b[1]),
          "f"(c0), "f"(c1), "f"(c2), "f"(c3));
}
// D += A*B
__device__ __forceinline__ void mma_acc(float* d, const u32* a, const u32* b) {
    asm("mma.sync.aligned.m16n8k8.row.col.f32.tf32.tf32.f32 "
        "{%0,%1,%2,%3}, {%4,%5,%6,%7}, {%8,%9}, {%0,%1,%2,%3};"
        : "+f"(d[0]), "+f"(d[1]), "+f"(d[2]), "+f"(d[3])
        : "r"(a[0]), "r"(a[1]), "r"(a[2]), "r"(a[3]), "r"(b[0]), "r"(b[1]));
}

// W' column c (warp-local, interleaved gate order), K-index k.
// c in [0,20): gate g=c&3, unit u=5w+(c>>2) -> W_hh[g*H+u][k]
// c==20 && warp 0: W_lin row (the fused linear head). Else 0 (pad).
__device__ __forceinline__ float wval(int w, int c, int k,
                                      const float* W_hh, const float* W_lin) {
    if (k >= H) return 0.0f;
    if (c < H)  return W_hh[(size_t)(((c & 3) * H) + (5 * w + (c >> 2))) * H + k];
    if (c == H && w == 0) return W_lin[k];
    return 0.0f;
}
__device__ __forceinline__ float biasval(int w, int c, const float* b_ih,
                                         const float* b_hh, const float* b_lin) {
    if (c < H) { int r = (c & 3) * H + (5 * w + (c >> 2)); return b_ih[r] + b_hh[r]; }
    if (c == H && w == 0) return b_lin[0];
    return 0.0f;
}
__device__ __forceinline__ float wxval(int w, int c, const float* W_ih) {
    if (c < H) return W_ih[(c & 3) * H + (5 * w + (c >> 2))];
    return 0.0f;   // head col: no x term
}

__global__ __launch_bounds__(THREADS, 4) void lstm_mma(
    const float* __restrict__ x,     const float* __restrict__ W_ih,
    const float* __restrict__ W_hh,  const float* __restrict__ b_ih,
    const float* __restrict__ b_hh,  const float* __restrict__ W_lin,
    const float* __restrict__ b_lin, float* __restrict__ out)
{
    __shared__ float  xs[BPB * XP];            // staged x rows (~33 KB)
    __shared__ float2 hbuf[2][BPB][H + 1];     // h split (tf32-hi, tf32-lo), dbl-buffered

    const int tid  = threadIdx.x;
    const int warp = tid >> 5;
    const int lane = tid & 31;
    const int m    = lane & 3;
    const int q    = lane >> 2;            // 0..7
    const int gb0  = blockIdx.x * BPB;

    // ---- stage x (coalesced float4) ----
    for (int i = tid; i < BPB * (SEQ / 4); i += THREADS) {
        int b = i >> 7, s = i & 127;       // SEQ/4 = 128
        ((float4*)(xs + b * XP))[s] =
            ((const float4*)(x + (size_t)(gb0 + b) * SEQ))[s];
    }
    for (int i = tid; i < BPB * (H + 1); i += THREADS)
        hbuf[0][i / (H + 1)][i % (H + 1)] = make_float2(0.0f, 0.0f);

    // ---- build constant B fragments (weights), bias, x-weights ----
    u32 Bhi[3][3][2], Blo[3][3][2];        // [kt][nt][reg]
    float bias0[3], bias1[3], wx0[3], wx1[3];
#pragma unroll
    for (int nt = 0; nt < 3; ++nt) {
        int ccol = q + 8 * nt;             // B fragment col = l/4 + 8*nt
#pragma unroll
        for (int kt = 0; kt < 3; ++kt) {
#pragma unroll
            for (int r = 0; r < 2; ++r) {
                int k = m + 4 * r + 8 * kt;
                float v = wval(warp, ccol, k, W_hh, W_lin);
                u32 hi = cvt_tf32(v);
                Bhi[kt][nt][r] = hi;
                Blo[kt][nt][r] = cvt_tf32(v - __uint_as_float(hi));
            }
        }
        int cA = 8 * nt + 2 * m, cB = cA + 1;   // D-fragment cols for this lane
        bias0[nt] = biasval(warp, cA, b_ih, b_hh, b_lin);
        bias1[nt] = biasval(warp, cB, b_ih, b_hh, b_lin);
        wx0[nt] = wxval(warp, cA, W_ih);
        wx1[nt] = wxval(warp, cB, W_ih);
    }

    const bool pairlow = ((m & 1) == 0);    // holds (i,f); partner holds (g,o)
    const int  bkeep   = pairlow ? q : q + 8;
    float cst[3] = {0.0f, 0.0f, 0.0f};

    __syncthreads();

    int p = 0;
#pragma unroll 1
    for (int t = 0; t < SEQ; ++t) {
        // ---- A fragments (h split) from hbuf[p] ----
        u32 Ahi[3][4], Alo[3][4];
#pragma unroll
        for (int kt = 0; kt < 3; ++kt) {
            int k0 = 8 * kt + m;
            float2 v0 = hbuf[p][q][k0];
            float2 v1 = hbuf[p][q + 8][k0];
            Ahi[kt][0] = __float_as_uint(v0.x); Alo[kt][0] = __float_as_uint(v0.y);
            Ahi[kt][1] = __float_as_uint(v1.x); Alo[kt][1] = __float_as_uint(v1.y);
            if (kt < 2) {
                float2 v2 = hbuf[p][q][k0 + 4];
                float2 v3 = hbuf[p][q + 8][k0 + 4];
                Ahi[kt][2] = __float_as_uint(v2.x); Alo[kt][2] = __float_as_uint(v2.y);
                Ahi[kt][3] = __float_as_uint(v3.x); Alo[kt][3] = __float_as_uint(v3.y);
            } else {
                Ahi[kt][2] = 0u; Alo[kt][2] = 0u;   // K pad 20..23
                Ahi[kt][3] = 0u; Alo[kt][3] = 0u;
            }
        }
        float xlo = xs[q * XP + t];
        float xhi = xs[(q + 8) * XP + t];

        // ---- gates GEMM: 3xTF32 (hi*hi + lo*hi + hi*lo), bias in first C ----
        float D[3][4];
#pragma unroll
        for (int nt = 0; nt < 3; ++nt) {
            mma_init(D[nt], Ahi[0], Bhi[0][nt], bias0[nt], bias1[nt], bias0[nt], bias1[nt]);
            mma_acc(D[nt], Alo[0], Bhi[0][nt]);
            mma_acc(D[nt], Ahi[0], Blo[0][nt]);
#pragma unroll
            for (int kt = 1; kt < 3; ++kt) {
                mma_acc(D[nt], Ahi[kt], Bhi[kt][nt]);
                mma_acc(D[nt], Alo[kt], Bhi[kt][nt]);
                mma_acc(D[nt], Ahi[kt], Blo[kt][nt]);
            }
            // x contribution (head col has wx=0)
            D[nt][0] = fmaf(wx0[nt], xlo, D[nt][0]);
            D[nt][1] = fmaf(wx1[nt], xlo, D[nt][1]);
            D[nt][2] = fmaf(wx0[nt], xhi, D[nt][2]);
            D[nt][3] = fmaf(wx1[nt], xhi, D[nt][3]);
        }

        // ---- fused linear head: col 20 of warp 0 = W_lin . h_{t-1} + b_lin ----
        if (warp == 0 && m == 2 && t > 0) {
            out[(size_t)(gb0 + q) * SEQ + (t - 1)]     = D[2][0];
            out[(size_t)(gb0 + q + 8) * SEQ + (t - 1)] = D[2][2];
        }

        // ---- epilogue: pair exchange + activations + state update ----
#pragma unroll
        for (int nt = 0; nt < 3; ++nt) {
            float sA = pairlow ? D[nt][2] : D[nt][0];
            float sB = pairlow ? D[nt][3] : D[nt][1];
            float rA = __shfl_xor_sync(0xffffffffu, sA, 1);
            float rB = __shfl_xor_sync(0xffffffffu, sB, 1);
            float gi = pairlow ? D[nt][0] : rA;
            float gf = pairlow ? D[nt][1] : rB;
            float gg = pairlow ? rA : D[nt][2];
            float go = pairlow ? rB : D[nt][3];
            int uloc = 2 * nt + (m >> 1);
            if (uloc < 5) {
                float iv = sigmoidf_(gi);
                float fv = sigmoidf_(gf);
                float gv = tanhf_(gg);
                float ov = sigmoidf_(go);
                cst[nt] = fmaf(fv, cst[nt], iv * gv);
                float h = ov * tanhf_(cst[nt]);
                u32 hi = cvt_tf32(h);
                float hif = __uint_as_float(hi);
                float lof = __uint_as_float(cvt_tf32(h - hif));
                hbuf[p ^ 1][bkeep][5 * warp + uloc] = make_float2(hif, lof);
            }
        }
        __syncthreads();
        p ^= 1;
    }

    // ---- final timestep of the head: out[:,511] from h_511 (= hbuf[p]) ----
    if (warp == 0 && lane < BPB) {
        float acc = b_lin[0];
#pragma unroll
        for (int u = 0; u < H; ++u) {
            float2 hv = hbuf[p][lane][u];
            acc = fmaf(hv.x + hv.y, W_lin[u], acc);
        }
        out[(size_t)(gb0 + lane) * SEQ + (SEQ - 1)] = acc;
    }
}

extern "C" void kernel_launch(void* const* d_in, const int* in_sizes, int n_in,
                              void* d_out, int out_size) {
    const float* x     = (const float*)d_in[0];
    const float* W_ih  = (const float*)d_in[1];
    const float* W_hh  = (const float*)d_in[2];
    const float* b_ih  = (const float*)d_in[3];
    const float* b_hh  = (const float*)d_in[4];
    const float* W_lin = (const float*)d_in[5];
    const float* b_lin = (const float*)d_in[6];
    float* out = (float*)d_out;

    lstm_mma<<<GRID, THREADS>>>(x, W_ih, W_hh, b_ih, b_hh, W_lin, b_lin, out);
}